// round 1
// baseline (speedup 1.0000x reference)
#include <cuda_runtime.h>
#include <cuda_bf16.h>

// Distral multi-head tiny MLP:
//   per head t (N = 32769):
//     h   = relu(W1[t] @ x[t] + b1[t])      (100,)
//     lo  = W2[t] @ h + b2[t]               (5,)
//     out = softmax(lo)
// Layouts (row-major, fp32):
//   x  : (N, 3)      W1 : (N, 100, 3)   b1 : (N, 100)
//   W2 : (N, 5, 100) b2 : (N, 5)        out: (N, 5)
//
// One warp per head. ~120 MB total traffic, streamed once -> HBM-bound.

#define HID 100
#define OUT 5

__global__ __launch_bounds__(256) void distral_kernel(
    const float* __restrict__ x,
    const float* __restrict__ W1,
    const float* __restrict__ b1,
    const float* __restrict__ W2,
    const float* __restrict__ b2,
    float* __restrict__ out,
    int n_heads)
{
    int gwarp = (blockIdx.x * blockDim.x + threadIdx.x) >> 5;
    int lane  = threadIdx.x & 31;
    if (gwarp >= n_heads) return;

    const float* w1 = W1 + (size_t)gwarp * (HID * 3);
    const float* w2 = W2 + (size_t)gwarp * (OUT * HID);
    const float* bb1 = b1 + (size_t)gwarp * HID;

    // x[t] — 3 values, broadcast within the warp (single L1 transaction each)
    float x0 = __ldg(x + (size_t)gwarp * 3 + 0);
    float x1 = __ldg(x + (size_t)gwarp * 3 + 1);
    float x2 = __ldg(x + (size_t)gwarp * 3 + 2);

    // hidden layer: lane handles j = lane + 32m, m = 0..3 (j < 100)
    float h[4];
    #pragma unroll
    for (int m = 0; m < 4; m++) {
        int j = lane + 32 * m;
        if (j < HID) {
            float v = fmaf(__ldg(w1 + j * 3 + 0), x0,
                      fmaf(__ldg(w1 + j * 3 + 1), x1,
                      fmaf(__ldg(w1 + j * 3 + 2), x2, __ldg(bb1 + j))));
            h[m] = fmaxf(v, 0.0f);
        } else {
            h[m] = 0.0f;
        }
    }

    // output layer: coalesced W2 loads + warp butterfly reduce per output
    float logits[OUT];
    #pragma unroll
    for (int o = 0; o < OUT; o++) {
        float p = 0.0f;
        #pragma unroll
        for (int m = 0; m < 4; m++) {
            int j = lane + 32 * m;
            if (j < HID) p = fmaf(__ldg(w2 + o * HID + j), h[m], p);
        }
        #pragma unroll
        for (int s = 16; s; s >>= 1)
            p += __shfl_xor_sync(0xffffffffu, p, s);
        logits[o] = p + __ldg(b2 + (size_t)gwarp * OUT + o);
    }

    // softmax over 5 (every lane has all logits after the full butterfly)
    float mx = logits[0];
    #pragma unroll
    for (int o = 1; o < OUT; o++) mx = fmaxf(mx, logits[o]);
    float e[OUT], sum = 0.0f;
    #pragma unroll
    for (int o = 0; o < OUT; o++) { e[o] = __expf(logits[o] - mx); sum += e[o]; }
    float inv = __frcp_rn(sum);

    if (lane < OUT)
        out[(size_t)gwarp * OUT + lane] = e[lane] * inv;
}

extern "C" void kernel_launch(void* const* d_in, const int* in_sizes, int n_in,
                              void* d_out, int out_size)
{
    const float* x  = (const float*)d_in[0];
    const float* W1 = (const float*)d_in[1];
    const float* b1 = (const float*)d_in[2];
    const float* W2 = (const float*)d_in[3];
    const float* b2 = (const float*)d_in[4];
    float* out = (float*)d_out;

    int n_heads = in_sizes[0] / 3;           // x is (N, 3)
    int warps_per_block = 256 / 32;          // 8
    int blocks = (n_heads + warps_per_block - 1) / warps_per_block;

    distral_kernel<<<blocks, 256>>>(x, W1, b1, W2, b2, out, n_heads);
}